// round 3
// baseline (speedup 1.0000x reference)
#include <cuda_runtime.h>

#define NN 50000
#define NE 800000
#define KDIN 64
#define KDH 128
#define EPSV 1e-5f
#define SLOPE 0.1f
#define NB_SCAN 49   // ceil(50000/1024)

// ---------------- scratch (device globals; no runtime allocation) ----------
__device__ __align__(256) int   g_cnt[NN];          // counts -> cursor
__device__ __align__(256) int   g_rowptr[NN + 1];
__device__ __align__(256) int   g_blocksum[64];
__device__ __align__(256) int   g_esrc[NE];         // CSR: src per sorted edge
__device__ __align__(256) float g_ecoef[NE];        // CSR: ew * dinv[src]
__device__ __align__(256) float g_deg[NN];
__device__ __align__(256) float g_dinv[NN];
__device__ __align__(256) float g_aggx[(size_t)NN * KDIN];
__device__ __align__(256) float g_h[(size_t)NN * KDH];
__device__ __align__(256) float g_res[(size_t)NN * KDH];
__device__ __align__(256) float g_agg1[(size_t)NN * KDH];
// stats: [0..127]=sum0 [128..255]=sumsq0 [256..383]=a0 [384..511]=sh0, +512 for layer 1
__device__ __align__(256) float g_stats[1024];

// ---------------- helpers --------------------------------------------------
__device__ __forceinline__ unsigned long long fma2(unsigned long long a,
                                                   unsigned long long b,
                                                   unsigned long long c) {
    unsigned long long d;
    asm("fma.rn.f32x2 %0, %1, %2, %3;" : "=l"(d) : "l"(a), "l"(b), "l"(c));
    return d;
}
__device__ __forceinline__ unsigned long long pack2(float x) {
    unsigned long long d;
    asm("mov.b64 %0, {%1, %1};" : "=l"(d) : "f"(x));
    return d;
}
__device__ __forceinline__ float2 unpack2(unsigned long long v) {
    float2 r;
    asm("mov.b64 {%0, %1}, %2;" : "=f"(r.x), "=f"(r.y) : "l"(v));
    return r;
}
__device__ __forceinline__ float leaky(float v) { return v > 0.f ? v : SLOPE * v; }

// ---------------- 1. init --------------------------------------------------
__global__ void k_init() {
    int i = blockIdx.x * blockDim.x + threadIdx.x;
    if (i < NN) { g_cnt[i] = 0; g_deg[i] = 1.0f; }  // deg starts at self-loop weight
    if (i < 1024) g_stats[i] = 0.0f;
}

// ---------------- 2. degree + counts --------------------------------------
__global__ void k_count(const int* __restrict__ dst, const float* __restrict__ ew) {
    int e = blockIdx.x * blockDim.x + threadIdx.x;
    if (e >= NE) return;
    int d = dst[e];
    atomicAdd(&g_cnt[d], 1);
    atomicAdd(&g_deg[d], ew[e]);
}

// ---------------- 3-5. scan (build rowptr, cursor, dinv) -------------------
__global__ void k_scan1() {
    __shared__ int sh[1024];
    int t = threadIdx.x;
    int i = blockIdx.x * 1024 + t;
    int v = (i < NN) ? g_cnt[i] : 0;
    sh[t] = v;
    __syncthreads();
    for (int off = 1; off < 1024; off <<= 1) {
        int a = (t >= off) ? sh[t - off] : 0;
        __syncthreads();
        sh[t] += a;
        __syncthreads();
    }
    if (i < NN) g_rowptr[i + 1] = sh[t];   // chunk-local inclusive
    if (t == 1023) g_blocksum[blockIdx.x] = sh[1023];
}
__global__ void k_scan2() {
    __shared__ int sh[64];
    int t = threadIdx.x;
    int v = (t < NB_SCAN) ? g_blocksum[t] : 0;
    sh[t] = v;
    __syncthreads();
    for (int off = 1; off < 64; off <<= 1) {
        int a = (t >= off) ? sh[t - off] : 0;
        __syncthreads();
        sh[t] += a;
        __syncthreads();
    }
    if (t < NB_SCAN) g_blocksum[t] = sh[t];
}
__global__ void k_scan3() {
    int i = blockIdx.x * blockDim.x + threadIdx.x;
    if (i >= NN) return;
    int b = i >> 10;
    int incl = g_rowptr[i + 1] + (b ? g_blocksum[b - 1] : 0);
    int cur = incl - g_cnt[i];
    g_rowptr[i + 1] = incl;
    g_cnt[i] = cur;                 // cursor = final exclusive prefix
    if (i == 0) g_rowptr[0] = 0;
    g_dinv[i] = rsqrtf(g_deg[i]);   // deg >= 1 always (self loop)
}

// ---------------- 6. CSR fill (pre-fold dinv[src]*ew) ----------------------
__global__ void k_fill(const int* __restrict__ src, const int* __restrict__ dst,
                       const float* __restrict__ ew) {
    int e = blockIdx.x * blockDim.x + threadIdx.x;
    if (e >= NE) return;
    int d = dst[e];
    int pos = atomicAdd(&g_cnt[d], 1);
    int s = src[e];
    g_esrc[pos] = s;
    g_ecoef[pos] = ew[e] * g_dinv[s];
}

// ---------------- 7. layer-0 aggregation (pull, 64-dim, warp/node) ---------
__global__ void k_agg0(const float* __restrict__ x) {
    int gt = blockIdx.x * blockDim.x + threadIdx.x;
    int node = gt >> 5, lane = gt & 31;
    if (node >= NN) return;
    float dd = g_dinv[node];
    const float2* x2 = (const float2*)x;
    float2 sv = x2[(size_t)node * 32 + lane];
    float c0 = dd * dd;
    float ax = c0 * sv.x, ay = c0 * sv.y;
    int p = g_rowptr[node], pe = g_rowptr[node + 1];
    for (; p < pe; ++p) {
        int s = g_esrc[p];
        float cc = dd * g_ecoef[p];
        float2 v = x2[(size_t)s * 32 + lane];
        ax = fmaf(cc, v.x, ax);
        ay = fmaf(cc, v.y, ay);
    }
    float2 o; o.x = ax; o.y = ay;
    ((float2*)g_aggx)[(size_t)node * 32 + lane] = o;
}

// ---------------- 12. layer-1 aggregation (pull, 128-dim, warp/node) -------
__global__ void k_agg1() {
    int gt = blockIdx.x * blockDim.x + threadIdx.x;
    int node = gt >> 5, lane = gt & 31;
    if (node >= NN) return;
    float dd = g_dinv[node];
    const float4* h4 = (const float4*)g_h;
    float4 sv = h4[(size_t)node * 32 + lane];
    float c0 = dd * dd;
    float4 acc;
    acc.x = c0 * sv.x; acc.y = c0 * sv.y; acc.z = c0 * sv.z; acc.w = c0 * sv.w;
    int p = g_rowptr[node], pe = g_rowptr[node + 1];
    for (; p < pe; ++p) {
        int s = g_esrc[p];
        float cc = dd * g_ecoef[p];
        float4 v = h4[(size_t)s * 32 + lane];
        acc.x = fmaf(cc, v.x, acc.x);
        acc.y = fmaf(cc, v.y, acc.y);
        acc.z = fmaf(cc, v.z, acc.z);
        acc.w = fmaf(cc, v.w, acc.w);
    }
    ((float4*)g_agg1)[(size_t)node * 32 + lane] = acc;
}

// ---------------- GEMM: C[N,128] = A[N,K] @ W[K,128] + bias ----------------
// 64-row block tile, 256 threads, thread tile = 8 rows x 4 cols, FFMA2 packed.
template <int K, bool STATS>
__device__ __forceinline__ void gemm_body(const float* __restrict__ A,
                                          const float* __restrict__ Wg,
                                          const float* __restrict__ bias,
                                          float* __restrict__ C,
                                          float* stats) {
    __shared__ float Ws[64 * 128];   // 32 KB (one 64-K phase of weights)
    __shared__ float As[64 * 64];    // 16 KB
    const int tid = threadIdx.x;
    const int colt = tid & 31;
    const int rowt = tid >> 5;
    const int c0 = colt * 4;
    const int rblk = blockIdx.x * 64;

    unsigned long long acc[8][2];
#pragma unroll
    for (int i = 0; i < 8; i++) { acc[i][0] = 0ull; acc[i][1] = 0ull; }

    for (int kk = 0; kk < K; kk += 64) {
        const float4* Wsrc = (const float4*)(Wg + (size_t)kk * 128);
#pragma unroll
        for (int i = tid; i < 2048; i += 256) ((float4*)Ws)[i] = Wsrc[i];
        for (int i = tid; i < 1024; i += 256) {
            int r = i >> 4, cc = i & 15;
            int gr = rblk + r;
            float4 v = make_float4(0.f, 0.f, 0.f, 0.f);
            if (gr < NN) v = ((const float4*)(A + (size_t)gr * K + kk))[cc];
            ((float4*)As)[i] = v;
        }
        __syncthreads();
#pragma unroll 16
        for (int k = 0; k < 64; k++) {
            const ulonglong2 wv = *(const ulonglong2*)(Ws + k * 128 + c0);
#pragma unroll
            for (int i = 0; i < 8; i++) {
                float a = As[(rowt * 8 + i) * 64 + k];
                unsigned long long aa = pack2(a);
                acc[i][0] = fma2(aa, wv.x, acc[i][0]);
                acc[i][1] = fma2(aa, wv.y, acc[i][1]);
            }
        }
        __syncthreads();
    }

    float4 bv = *(const float4*)(bias + c0);
    float4 s = make_float4(0.f, 0.f, 0.f, 0.f);
    float4 s2 = make_float4(0.f, 0.f, 0.f, 0.f);
#pragma unroll
    for (int i = 0; i < 8; i++) {
        int r = rblk + rowt * 8 + i;
        if (r < NN) {
            float2 p01 = unpack2(acc[i][0]);
            float2 p23 = unpack2(acc[i][1]);
            float4 v = make_float4(p01.x + bv.x, p01.y + bv.y, p23.x + bv.z, p23.y + bv.w);
            ((float4*)C)[(size_t)r * 32 + colt] = v;
            if (STATS) {
                s.x += v.x; s.y += v.y; s.z += v.z; s.w += v.w;
                s2.x += v.x * v.x; s2.y += v.y * v.y;
                s2.z += v.z * v.z; s2.w += v.w * v.w;
            }
        }
    }
    if (STATS) {
        atomicAdd(&stats[c0 + 0], s.x);  atomicAdd(&stats[c0 + 1], s.y);
        atomicAdd(&stats[c0 + 2], s.z);  atomicAdd(&stats[c0 + 3], s.w);
        atomicAdd(&stats[128 + c0 + 0], s2.x); atomicAdd(&stats[128 + c0 + 1], s2.y);
        atomicAdd(&stats[128 + c0 + 2], s2.z); atomicAdd(&stats[128 + c0 + 3], s2.w);
    }
}

__global__ void __launch_bounds__(256) k_gemm0h(const float* __restrict__ W,
                                                const float* __restrict__ b) {
    gemm_body<64, true>(g_aggx, W, b, g_h, g_stats);
}
__global__ void __launch_bounds__(256) k_gemmres(const float* __restrict__ xin,
                                                 const float* __restrict__ W,
                                                 const float* __restrict__ b) {
    gemm_body<64, false>(xin, W, b, g_res, nullptr);
}
__global__ void __launch_bounds__(256) k_gemm1(const float* __restrict__ W,
                                               const float* __restrict__ b) {
    gemm_body<128, true>(g_agg1, W, b, g_h, g_stats + 512);
}

// ---------------- BN finalize (128 threads) --------------------------------
__global__ void k_bnfin(const float* __restrict__ g, const float* __restrict__ be, int off) {
    int c = threadIdx.x;
    float* st = g_stats + off;
    float invn = 1.0f / (float)NN;
    float mu = st[c] * invn;
    float var = st[128 + c] * invn - mu * mu;
    float inv = rsqrtf(var + EPSV);
    float a = g[c] * inv;
    st[256 + c] = a;
    st[384 + c] = be[c] - mu * a;
}

// ---------------- post layer-0: h = leaky(bn(h)) + res (in place) ----------
__global__ void k_post0() {
    int i = blockIdx.x * blockDim.x + threadIdx.x;
    if (i >= NN * 32) return;
    int col4 = (i & 31) * 4;
    float4 a = *(const float4*)&g_stats[256 + col4];
    float4 sh = *(const float4*)&g_stats[384 + col4];
    float4 h = ((const float4*)g_h)[i];
    float4 r = ((const float4*)g_res)[i];
    float4 v;
    v.x = leaky(fmaf(a.x, h.x, sh.x)) + r.x;
    v.y = leaky(fmaf(a.y, h.y, sh.y)) + r.y;
    v.z = leaky(fmaf(a.z, h.z, sh.z)) + r.z;
    v.w = leaky(fmaf(a.w, h.w, sh.w)) + r.w;
    ((float4*)g_h)[i] = v;
}

// ---------------- final: bn1 + leaky + res + layernorm ---------------------
__global__ void k_final(float* __restrict__ out) {
    int gt = blockIdx.x * blockDim.x + threadIdx.x;
    int row = gt >> 5, lane = gt & 31;
    if (row >= NN) return;
    int col4 = lane * 4;
    float4 a = *(const float4*)&g_stats[512 + 256 + col4];
    float4 sh = *(const float4*)&g_stats[512 + 384 + col4];
    float4 h = ((const float4*)g_h)[(size_t)row * 32 + lane];
    float4 r = ((const float4*)g_res)[(size_t)row * 32 + lane];
    float4 v;
    v.x = leaky(fmaf(a.x, h.x, sh.x)) + r.x;
    v.y = leaky(fmaf(a.y, h.y, sh.y)) + r.y;
    v.z = leaky(fmaf(a.z, h.z, sh.z)) + r.z;
    v.w = leaky(fmaf(a.w, h.w, sh.w)) + r.w;
    float s = v.x + v.y + v.z + v.w;
    float s2 = v.x * v.x + v.y * v.y + v.z * v.z + v.w * v.w;
#pragma unroll
    for (int m = 16; m; m >>= 1) {
        s += __shfl_xor_sync(0xffffffffu, s, m);
        s2 += __shfl_xor_sync(0xffffffffu, s2, m);
    }
    float mu = s * (1.0f / 128.0f);
    float var = s2 * (1.0f / 128.0f) - mu * mu;
    float w = rsqrtf(var + EPSV);
    float4 o;
    o.x = (v.x - mu) * w; o.y = (v.y - mu) * w;
    o.z = (v.z - mu) * w; o.w = (v.w - mu) * w;
    ((float4*)out)[(size_t)row * 32 + lane] = o;
}

// ---------------- launch ----------------------------------------------------
extern "C" void kernel_launch(void* const* d_in, const int* in_sizes, int n_in,
                              void* d_out, int out_size) {
    const float* x    = (const float*)d_in[0];
    const int*   src  = (const int*)d_in[1];
    const int*   dst  = (const int*)d_in[2];
    const float* ew   = (const float*)d_in[3];
    const float* W0   = (const float*)d_in[4];
    const float* b0   = (const float*)d_in[5];
    const float* g0   = (const float*)d_in[6];
    const float* be0  = (const float*)d_in[7];
    const float* W1   = (const float*)d_in[8];
    const float* b1   = (const float*)d_in[9];
    const float* g1   = (const float*)d_in[10];
    const float* be1  = (const float*)d_in[11];
    const float* Wres = (const float*)d_in[12];
    const float* bres = (const float*)d_in[13];
    float* out = (float*)d_out;

    const int gN   = (NN + 255) / 256;        // 196
    const int gE   = (NE + 255) / 256;        // 3125
    const int gW   = (NN * 32) / 256;         // 6250 (warp-per-node kernels)
    const int gM   = (NN + 63) / 64;          // 782 (GEMM blocks)

    k_init<<<gN, 256>>>();
    k_count<<<gE, 256>>>(dst, ew);
    k_scan1<<<NB_SCAN, 1024>>>();
    k_scan2<<<1, 64>>>();
    k_scan3<<<gN, 256>>>();
    k_fill<<<gE, 256>>>(src, dst, ew);
    k_agg0<<<gW, 256>>>(x);
    k_gemm0h<<<gM, 256>>>(W0, b0);
    k_gemmres<<<gM, 256>>>(x, Wres, bres);
    k_bnfin<<<1, 128>>>(g0, be0, 0);
    k_post0<<<gW, 256>>>();
    k_agg1<<<gW, 256>>>();
    k_gemm1<<<gM, 256>>>(W1, b1);
    k_bnfin<<<1, 128>>>(g1, be1, 512);
    k_final<<<gW, 256>>>(out);
}

// round 4
// speedup vs baseline: 3.1753x; 3.1753x over previous
#include <cuda_runtime.h>

typedef unsigned long long ull;

#define NN 50000
#define NE 800000
#define KDH 128
#define EPSV 1e-5f
#define SLOPE 0.1f
#define NB_SCAN 49   // ceil(50000/1024)
#define GM 782       // ceil(50000/64) gemm row-blocks

// ---------------- scratch (device globals; no runtime allocation) ----------
__device__ __align__(256) int   g_cnt[NN];
__device__ __align__(256) int   g_rowptr[NN + 1];
__device__ __align__(256) int   g_blocksum[64];
__device__ __align__(256) ull   g_epack[NE];        // packed (src:int low, coef:float high)
__device__ __align__(256) float g_deg[NN];
__device__ __align__(256) float g_dinv[NN];
__device__ __align__(256) float g_aggx[(size_t)NN * 64];
__device__ __align__(256) float g_h[(size_t)NN * KDH];
__device__ __align__(256) float g_res[(size_t)NN * KDH];
__device__ __align__(256) float g_agg1[(size_t)NN * KDH];
// stats: [0..127]=sum0 [128..255]=sumsq0 [256..383]=a0 [384..511]=sh0, +512 layer1
__device__ __align__(256) float g_stats[1024];

// ---------------- helpers --------------------------------------------------
__device__ __forceinline__ ull fma2(ull a, ull b, ull c) {
    ull d;
    asm("fma.rn.f32x2 %0, %1, %2, %3;" : "=l"(d) : "l"(a), "l"(b), "l"(c));
    return d;
}
__device__ __forceinline__ ull pack2(float x) {
    ull d;
    asm("mov.b64 %0, {%1, %1};" : "=l"(d) : "f"(x));
    return d;
}
__device__ __forceinline__ float2 unpack2(ull v) {
    float2 r;
    asm("mov.b64 {%0, %1}, %2;" : "=f"(r.x), "=f"(r.y) : "l"(v));
    return r;
}
__device__ __forceinline__ float leaky(float v) { return v > 0.f ? v : SLOPE * v; }

// ---------------- 1. init --------------------------------------------------
__global__ void k_init() {
    int i = blockIdx.x * blockDim.x + threadIdx.x;
    if (i < NN) { g_cnt[i] = 0; g_deg[i] = 1.0f; }
    if (i < 1024) g_stats[i] = 0.0f;
}

// ---------------- 2. degree + counts ---------------------------------------
__global__ void k_count(const int* __restrict__ dst, const float* __restrict__ ew) {
    int e = blockIdx.x * blockDim.x + threadIdx.x;
    if (e >= NE) return;
    int d = dst[e];
    atomicAdd(&g_cnt[d], 1);
    atomicAdd(&g_deg[d], ew[e]);
}

// ---------------- 3-5. scan ------------------------------------------------
__global__ void k_scan1() {
    __shared__ int sh[1024];
    int t = threadIdx.x;
    int i = blockIdx.x * 1024 + t;
    int v = (i < NN) ? g_cnt[i] : 0;
    sh[t] = v;
    __syncthreads();
    for (int off = 1; off < 1024; off <<= 1) {
        int a = (t >= off) ? sh[t - off] : 0;
        __syncthreads();
        sh[t] += a;
        __syncthreads();
    }
    if (i < NN) g_rowptr[i + 1] = sh[t];
    if (t == 1023) g_blocksum[blockIdx.x] = sh[1023];
}
__global__ void k_scan2() {
    __shared__ int sh[64];
    int t = threadIdx.x;
    int v = (t < NB_SCAN) ? g_blocksum[t] : 0;
    sh[t] = v;
    __syncthreads();
    for (int off = 1; off < 64; off <<= 1) {
        int a = (t >= off) ? sh[t - off] : 0;
        __syncthreads();
        sh[t] += a;
        __syncthreads();
    }
    if (t < NB_SCAN) g_blocksum[t] = sh[t];
}
__global__ void k_scan3() {
    int i = blockIdx.x * blockDim.x + threadIdx.x;
    if (i >= NN) return;
    int b = i >> 10;
    int incl = g_rowptr[i + 1] + (b ? g_blocksum[b - 1] : 0);
    int cur = incl - g_cnt[i];
    g_rowptr[i + 1] = incl;
    g_cnt[i] = cur;
    if (i == 0) g_rowptr[0] = 0;
    g_dinv[i] = rsqrtf(g_deg[i]);
}

// ---------------- 6. CSR fill: pack (src, ew*dinv[src]*dinv[dst]) ----------
__global__ void k_fill(const int* __restrict__ src, const int* __restrict__ dst,
                       const float* __restrict__ ew) {
    int e = blockIdx.x * blockDim.x + threadIdx.x;
    if (e >= NE) return;
    int d = dst[e];
    int pos = atomicAdd(&g_cnt[d], 1);
    int s = src[e];
    float coef = ew[e] * g_dinv[s] * g_dinv[d];
    ull pk = (ull)(unsigned)s | ((ull)__float_as_uint(coef) << 32);
    g_epack[pos] = pk;
}

// ---------------- 7. layer-0 aggregation (64-dim, warp/node, unroll4) ------
__global__ void k_agg0(const float* __restrict__ x) {
    int gt = blockIdx.x * blockDim.x + threadIdx.x;
    int node = gt >> 5, lane = gt & 31;
    if (node >= NN) return;
    float dd = g_dinv[node];
    const float2* x2 = (const float2*)x;
    float2 sv = __ldg(&x2[(size_t)node * 32 + lane]);
    float cs = dd * dd;
    float ax = cs * sv.x, ay = cs * sv.y;
    int p = g_rowptr[node], pe = g_rowptr[node + 1];
    for (; p + 4 <= pe; p += 4) {
        ull e0 = __ldg(&g_epack[p]);
        ull e1 = __ldg(&g_epack[p + 1]);
        ull e2 = __ldg(&g_epack[p + 2]);
        ull e3 = __ldg(&g_epack[p + 3]);
        int s0 = (int)(unsigned)e0, s1 = (int)(unsigned)e1;
        int s2 = (int)(unsigned)e2, s3 = (int)(unsigned)e3;
        float c0 = __uint_as_float((unsigned)(e0 >> 32));
        float c1 = __uint_as_float((unsigned)(e1 >> 32));
        float c2 = __uint_as_float((unsigned)(e2 >> 32));
        float c3 = __uint_as_float((unsigned)(e3 >> 32));
        float2 v0 = __ldg(&x2[(size_t)s0 * 32 + lane]);
        float2 v1 = __ldg(&x2[(size_t)s1 * 32 + lane]);
        float2 v2 = __ldg(&x2[(size_t)s2 * 32 + lane]);
        float2 v3 = __ldg(&x2[(size_t)s3 * 32 + lane]);
        ax = fmaf(c0, v0.x, ax); ay = fmaf(c0, v0.y, ay);
        ax = fmaf(c1, v1.x, ax); ay = fmaf(c1, v1.y, ay);
        ax = fmaf(c2, v2.x, ax); ay = fmaf(c2, v2.y, ay);
        ax = fmaf(c3, v3.x, ax); ay = fmaf(c3, v3.y, ay);
    }
    for (; p < pe; ++p) {
        ull e0 = __ldg(&g_epack[p]);
        int s0 = (int)(unsigned)e0;
        float c0 = __uint_as_float((unsigned)(e0 >> 32));
        float2 v0 = __ldg(&x2[(size_t)s0 * 32 + lane]);
        ax = fmaf(c0, v0.x, ax); ay = fmaf(c0, v0.y, ay);
    }
    float2 o; o.x = ax; o.y = ay;
    ((float2*)g_aggx)[(size_t)node * 32 + lane] = o;
}

// ---------------- 11. layer-1 aggregation (128-dim, warp/node, unroll4) ----
__global__ void k_agg1() {
    int gt = blockIdx.x * blockDim.x + threadIdx.x;
    int node = gt >> 5, lane = gt & 31;
    if (node >= NN) return;
    float dd = g_dinv[node];
    const float4* h4 = (const float4*)g_h;
    float4 sv = __ldg(&h4[(size_t)node * 32 + lane]);
    float cs = dd * dd;
    float4 acc;
    acc.x = cs * sv.x; acc.y = cs * sv.y; acc.z = cs * sv.z; acc.w = cs * sv.w;
    int p = g_rowptr[node], pe = g_rowptr[node + 1];
    for (; p + 4 <= pe; p += 4) {
        ull e0 = __ldg(&g_epack[p]);
        ull e1 = __ldg(&g_epack[p + 1]);
        ull e2 = __ldg(&g_epack[p + 2]);
        ull e3 = __ldg(&g_epack[p + 3]);
        int s0 = (int)(unsigned)e0, s1 = (int)(unsigned)e1;
        int s2 = (int)(unsigned)e2, s3 = (int)(unsigned)e3;
        float c0 = __uint_as_float((unsigned)(e0 >> 32));
        float c1 = __uint_as_float((unsigned)(e1 >> 32));
        float c2 = __uint_as_float((unsigned)(e2 >> 32));
        float c3 = __uint_as_float((unsigned)(e3 >> 32));
        float4 v0 = __ldg(&h4[(size_t)s0 * 32 + lane]);
        float4 v1 = __ldg(&h4[(size_t)s1 * 32 + lane]);
        float4 v2 = __ldg(&h4[(size_t)s2 * 32 + lane]);
        float4 v3 = __ldg(&h4[(size_t)s3 * 32 + lane]);
        acc.x = fmaf(c0, v0.x, acc.x); acc.y = fmaf(c0, v0.y, acc.y);
        acc.z = fmaf(c0, v0.z, acc.z); acc.w = fmaf(c0, v0.w, acc.w);
        acc.x = fmaf(c1, v1.x, acc.x); acc.y = fmaf(c1, v1.y, acc.y);
        acc.z = fmaf(c1, v1.z, acc.z); acc.w = fmaf(c1, v1.w, acc.w);
        acc.x = fmaf(c2, v2.x, acc.x); acc.y = fmaf(c2, v2.y, acc.y);
        acc.z = fmaf(c2, v2.z, acc.z); acc.w = fmaf(c2, v2.w, acc.w);
        acc.x = fmaf(c3, v3.x, acc.x); acc.y = fmaf(c3, v3.y, acc.y);
        acc.z = fmaf(c3, v3.z, acc.z); acc.w = fmaf(c3, v3.w, acc.w);
    }
    for (; p < pe; ++p) {
        ull e0 = __ldg(&g_epack[p]);
        int s0 = (int)(unsigned)e0;
        float c0 = __uint_as_float((unsigned)(e0 >> 32));
        float4 v0 = __ldg(&h4[(size_t)s0 * 32 + lane]);
        acc.x = fmaf(c0, v0.x, acc.x); acc.y = fmaf(c0, v0.y, acc.y);
        acc.z = fmaf(c0, v0.z, acc.z); acc.w = fmaf(c0, v0.w, acc.w);
    }
    ((float4*)g_agg1)[(size_t)node * 32 + lane] = acc;
}

// ---------------- GEMM v2: row-pair FFMA2, transposed A in smem ------------
struct GemmSmem {
    float Ws[32 * 128];   // 16KB  W phase, row-major [k][c]
    float Ast[32 * 64];   // 8KB   A phase, transposed [k][r]
    float sstat[256];     // 1KB   block-level BN stats
};

template <int K, bool STATS>
__device__ __forceinline__ void gemm_v2(GemmSmem& sm,
                                        const float* __restrict__ A,
                                        const float* __restrict__ Wg,
                                        const float* __restrict__ bias,
                                        float* __restrict__ C,
                                        int rblk) {
    const int tid = threadIdx.x;
    const int colt = tid & 31;
    const int rowt = tid >> 5;
    const int c0 = colt * 4;
    const int r0 = rowt * 8;

    if (STATS) sm.sstat[tid] = 0.0f;

    ull acc[4][4];
#pragma unroll
    for (int i = 0; i < 4; i++)
#pragma unroll
        for (int j = 0; j < 4; j++) acc[i][j] = 0ull;

    for (int kk = 0; kk < K; kk += 32) {
        const float4* Wsrc = (const float4*)(Wg + (size_t)kk * 128);
#pragma unroll
        for (int i = tid; i < 1024; i += 256) ((float4*)sm.Ws)[i] = __ldg(&Wsrc[i]);
#pragma unroll
        for (int it = 0; it < 2; it++) {
            int i = tid + it * 256;
            int r = i & 63, kq = i >> 6;
            float4 v = make_float4(0.f, 0.f, 0.f, 0.f);
            int gr = rblk + r;
            if (gr < NN) v = __ldg((const float4*)(A + (size_t)gr * K + kk) + kq);
            sm.Ast[(4 * kq + 0) * 64 + r] = v.x;
            sm.Ast[(4 * kq + 1) * 64 + r] = v.y;
            sm.Ast[(4 * kq + 2) * 64 + r] = v.z;
            sm.Ast[(4 * kq + 3) * 64 + r] = v.w;
        }
        __syncthreads();
#pragma unroll
        for (int k = 0; k < 32; k++) {
            float4 wv = *(const float4*)(sm.Ws + k * 128 + c0);
            ull w2[4];
            w2[0] = pack2(wv.x); w2[1] = pack2(wv.y);
            w2[2] = pack2(wv.z); w2[3] = pack2(wv.w);
            const ull* arow = (const ull*)(sm.Ast + k * 64 + r0);
            ull a2[4];
            a2[0] = arow[0]; a2[1] = arow[1]; a2[2] = arow[2]; a2[3] = arow[3];
#pragma unroll
            for (int rp = 0; rp < 4; rp++)
#pragma unroll
                for (int c = 0; c < 4; c++)
                    acc[rp][c] = fma2(a2[rp], w2[c], acc[rp][c]);
        }
        __syncthreads();
    }

    float4 bv = __ldg((const float4*)(bias + c0));
    float ss[4] = {0.f, 0.f, 0.f, 0.f};
    float sq[4] = {0.f, 0.f, 0.f, 0.f};
#pragma unroll
    for (int rp = 0; rp < 4; rp++) {
        float2 u0 = unpack2(acc[rp][0]);
        float2 u1 = unpack2(acc[rp][1]);
        float2 u2 = unpack2(acc[rp][2]);
        float2 u3 = unpack2(acc[rp][3]);
        int re = rblk + r0 + 2 * rp;
        float4 ve = make_float4(u0.x + bv.x, u1.x + bv.y, u2.x + bv.z, u3.x + bv.w);
        float4 vo = make_float4(u0.y + bv.x, u1.y + bv.y, u2.y + bv.z, u3.y + bv.w);
        if (re < NN) {
            ((float4*)C)[(size_t)re * 32 + colt] = ve;
            if (STATS) {
                ss[0] += ve.x; ss[1] += ve.y; ss[2] += ve.z; ss[3] += ve.w;
                sq[0] += ve.x * ve.x; sq[1] += ve.y * ve.y;
                sq[2] += ve.z * ve.z; sq[3] += ve.w * ve.w;
            }
        }
        if (re + 1 < NN) {
            ((float4*)C)[(size_t)(re + 1) * 32 + colt] = vo;
            if (STATS) {
                ss[0] += vo.x; ss[1] += vo.y; ss[2] += vo.z; ss[3] += vo.w;
                sq[0] += vo.x * vo.x; sq[1] += vo.y * vo.y;
                sq[2] += vo.z * vo.z; sq[3] += vo.w * vo.w;
            }
        }
    }
    if (STATS) {
#pragma unroll
        for (int j = 0; j < 4; j++) {
            atomicAdd(&sm.sstat[c0 + j], ss[j]);
            atomicAdd(&sm.sstat[128 + c0 + j], sq[j]);
        }
        __syncthreads();
    }
}

__global__ void __launch_bounds__(256) k_gemm0pair(const float* __restrict__ xin,
                                                   const float* __restrict__ W0,
                                                   const float* __restrict__ b0,
                                                   const float* __restrict__ Wres,
                                                   const float* __restrict__ bres) {
    __shared__ GemmSmem sm;
    if (blockIdx.x < GM) {
        gemm_v2<64, true>(sm, g_aggx, W0, b0, g_h, blockIdx.x * 64);
        atomicAdd(&g_stats[threadIdx.x], sm.sstat[threadIdx.x]);
    } else {
        gemm_v2<64, false>(sm, xin, Wres, bres, g_res, (blockIdx.x - GM) * 64);
    }
}

__global__ void __launch_bounds__(256) k_gemm1(const float* __restrict__ W,
                                               const float* __restrict__ b) {
    __shared__ GemmSmem sm;
    gemm_v2<128, true>(sm, g_agg1, W, b, g_h, blockIdx.x * 64);
    atomicAdd(&g_stats[512 + threadIdx.x], sm.sstat[threadIdx.x]);
}

// ---------------- BN finalize ----------------------------------------------
__global__ void k_bnfin(const float* __restrict__ g, const float* __restrict__ be, int off) {
    int c = threadIdx.x;
    float* st = g_stats + off;
    float invn = 1.0f / (float)NN;
    float mu = st[c] * invn;
    float var = st[128 + c] * invn - mu * mu;
    float inv = rsqrtf(var + EPSV);
    float a = g[c] * inv;
    st[256 + c] = a;
    st[384 + c] = be[c] - mu * a;
}

// ---------------- post layer-0: h = leaky(bn(h)) + res ---------------------
__global__ void k_post0() {
    int i = blockIdx.x * blockDim.x + threadIdx.x;
    if (i >= NN * 32) return;
    int col4 = (i & 31) * 4;
    float4 a = *(const float4*)&g_stats[256 + col4];
    float4 sh = *(const float4*)&g_stats[384 + col4];
    float4 h = ((const float4*)g_h)[i];
    float4 r = ((const float4*)g_res)[i];
    float4 v;
    v.x = leaky(fmaf(a.x, h.x, sh.x)) + r.x;
    v.y = leaky(fmaf(a.y, h.y, sh.y)) + r.y;
    v.z = leaky(fmaf(a.z, h.z, sh.z)) + r.z;
    v.w = leaky(fmaf(a.w, h.w, sh.w)) + r.w;
    ((float4*)g_h)[i] = v;
}

// ---------------- final: bn1 + leaky + res + layernorm ---------------------
__global__ void k_final(float* __restrict__ out) {
    int gt = blockIdx.x * blockDim.x + threadIdx.x;
    int row = gt >> 5, lane = gt & 31;
    if (row >= NN) return;
    int col4 = lane * 4;
    float4 a = *(const float4*)&g_stats[512 + 256 + col4];
    float4 sh = *(const float4*)&g_stats[512 + 384 + col4];
    float4 h = ((const float4*)g_h)[(size_t)row * 32 + lane];
    float4 r = ((const float4*)g_res)[(size_t)row * 32 + lane];
    float4 v;
    v.x = leaky(fmaf(a.x, h.x, sh.x)) + r.x;
    v.y = leaky(fmaf(a.y, h.y, sh.y)) + r.y;
    v.z = leaky(fmaf(a.z, h.z, sh.z)) + r.z;
    v.w = leaky(fmaf(a.w, h.w, sh.w)) + r.w;
    float s = v.x + v.y + v.z + v.w;
    float s2 = v.x * v.x + v.y * v.y + v.z * v.z + v.w * v.w;
#pragma unroll
    for (int m = 16; m; m >>= 1) {
        s += __shfl_xor_sync(0xffffffffu, s, m);
        s2 += __shfl_xor_sync(0xffffffffu, s2, m);
    }
    float mu = s * (1.0f / 128.0f);
    float var = s2 * (1.0f / 128.0f) - mu * mu;
    float w = rsqrtf(var + EPSV);
    float4 o;
    o.x = (v.x - mu) * w; o.y = (v.y - mu) * w;
    o.z = (v.z - mu) * w; o.w = (v.w - mu) * w;
    ((float4*)out)[(size_t)row * 32 + lane] = o;
}

// ---------------- launch ----------------------------------------------------
extern "C" void kernel_launch(void* const* d_in, const int* in_sizes, int n_in,
                              void* d_out, int out_size) {
    const float* x    = (const float*)d_in[0];
    const int*   src  = (const int*)d_in[1];
    const int*   dst  = (const int*)d_in[2];
    const float* ew   = (const float*)d_in[3];
    const float* W0   = (const float*)d_in[4];
    const float* b0   = (const float*)d_in[5];
    const float* g0   = (const float*)d_in[6];
    const float* be0  = (const float*)d_in[7];
    const float* W1   = (const float*)d_in[8];
    const float* b1   = (const float*)d_in[9];
    const float* g1   = (const float*)d_in[10];
    const float* be1  = (const float*)d_in[11];
    const float* Wres = (const float*)d_in[12];
    const float* bres = (const float*)d_in[13];
    float* out = (float*)d_out;

    const int gN = (NN + 255) / 256;   // 196
    const int gE = (NE + 255) / 256;   // 3125
    const int gW = (NN * 32) / 256;    // 6250

    k_init<<<gN, 256>>>();
    k_count<<<gE, 256>>>(dst, ew);
    k_scan1<<<NB_SCAN, 1024>>>();
    k_scan2<<<1, 64>>>();
    k_scan3<<<gN, 256>>>();
    k_fill<<<gE, 256>>>(src, dst, ew);
    k_agg0<<<gW, 256>>>(x);
    k_gemm0pair<<<2 * GM, 256>>>(x, W0, b0, Wres, bres);
    k_bnfin<<<1, 128>>>(g0, be0, 0);
    k_post0<<<gW, 256>>>();
    k_agg1<<<gW, 256>>>();
    k_gemm1<<<GM, 256>>>(W1, b1);
    k_bnfin<<<1, 128>>>(g1, be1, 512);
    k_final<<<gW, 256>>>(out);
}